// round 1
// baseline (speedup 1.0000x reference)
#include <cuda_runtime.h>

// ---------------------------------------------------------------------------
// MCA linear attention, fp32, built around packed fma.rn.f32x2 (FFMA2).
// B=8, C=64, H=W=160 -> N=25600 spatial, P=8 heads, d=8.
//
// Pass 1: k = softplus(wk@low+bk), v = wv@low+bv per pixel;
//         block-local reduce  attn[p,m,c] += k[p,m]*v[p,c],  ksum[p,m] += k[p,m]
//         then atomicAdd into __device__ scratch.
// Pass 2: q = softplus([wqh@high ; wql@low]); norm = 1/(q·(ksum+eps));
//         t = norm * (q @ attn); y = wo@t + bo  -> out.
// ---------------------------------------------------------------------------

#define DINL __device__ __forceinline__

namespace mca {

constexpr int Bn   = 8;
constexpr int Cc   = 64;
constexpr int Np   = 160 * 160;     // 25600
constexpr int BN   = Bn * Np;       // 204800
constexpr int TILE = 128;           // pixels per block-tile, threads per block
constexpr int TPB  = 128;
constexpr int NTILES = BN / TILE;   // 1600
constexpr int TPB_PER_BATCH = Np / TILE;  // 200
constexpr int PITCH = 129;          // padded smem row pitch (conflict-free)
constexpr float EPSV = 1e-6f;

// reduction scratch (no allocation allowed -> __device__ globals)
__device__ float g_attn[Bn * 64 * 8];   // [b][p*8+m][c]
__device__ float g_ksum[Bn * 64];       // [b][p*8+m]

typedef unsigned long long u64;

DINL u64 pk2(float lo, float hi) {
    u64 r;
    asm("mov.b64 %0, {%1, %2};" : "=l"(r) : "f"(lo), "f"(hi));
    return r;
}
DINL void upk2(u64 v, float& lo, float& hi) {
    asm("mov.b64 {%0, %1}, %2;" : "=f"(lo), "=f"(hi) : "l"(v));
}
DINL u64 ffma2(u64 a, u64 b, u64 c) {
    u64 d;
    asm("fma.rn.f32x2 %0, %1, %2, %3;" : "=l"(d) : "l"(a), "l"(b), "l"(c));
    return d;
}
DINL u64 fadd2(u64 a, u64 b) {
    u64 d;
    asm("add.rn.f32x2 %0, %1, %2;" : "=l"(d) : "l"(a), "l"(b));
    return d;
}

// 64-wide dot product: x packed as 32 f32x2 pairs, weight row in shared mem
// (16B-aligned). 4 independent accumulator chains for ILP.
DINL float dot64(const u64* x2, const float* wrow) {
    const ulonglong2* w = reinterpret_cast<const ulonglong2*>(wrow);
    u64 a0 = 0ull, a1 = 0ull, a2 = 0ull, a3 = 0ull;
#pragma unroll
    for (int i = 0; i < 8; i++) {
        ulonglong2 w0 = w[2 * i];
        ulonglong2 w1 = w[2 * i + 1];
        a0 = ffma2(w0.x, x2[4 * i + 0], a0);
        a1 = ffma2(w0.y, x2[4 * i + 1], a1);
        a2 = ffma2(w1.x, x2[4 * i + 2], a2);
        a3 = ffma2(w1.y, x2[4 * i + 3], a3);
    }
    a0 = fadd2(a0, a1);
    a2 = fadd2(a2, a3);
    a0 = fadd2(a0, a2);
    float lo, hi;
    upk2(a0, lo, hi);
    return lo + hi;
}

DINL float softplus(float x) {
    // log(1+exp(x)) stable form; conv outputs are O(1) so __expf is safe/accurate.
    return fmaxf(x, 0.0f) + log1pf(__expf(-fabsf(x)));
}

// ---------------------------------------------------------------------------
__global__ void zero_scratch() {
    for (int i = threadIdx.x; i < Bn * 64 * 8; i += blockDim.x) g_attn[i] = 0.0f;
    for (int i = threadIdx.x; i < Bn * 64; i += blockDim.x) g_ksum[i] = 0.0f;
}

// ---------------------------------------------------------------------------
// Pass 1: dynamic smem layout (floats):
//   [0,4096)        swk
//   [4096,8192)     swv
//   [8192,8256)     sbk
//   [8256,8320)     sbv
//   [8320,+64*129)  sK  [ch][pix] padded
//   [...,+64*129)   sV
__global__ __launch_bounds__(TPB)
void pass1_kv(const float* __restrict__ low,
              const float* __restrict__ wk, const float* __restrict__ bk,
              const float* __restrict__ wv, const float* __restrict__ bv) {
    extern __shared__ float sm[];
    float* swk = sm;
    float* swv = sm + 4096;
    float* sbk = sm + 8192;
    float* sbv = sm + 8256;
    float* sK  = sm + 8320;
    float* sV  = sK + 64 * PITCH;

    const int tid = threadIdx.x;

    // stage weights into shared (once per block; blocks are grid-stride persistent)
    {
        const float4* s0 = reinterpret_cast<const float4*>(wk);
        const float4* s1 = reinterpret_cast<const float4*>(wv);
        float4* d0 = reinterpret_cast<float4*>(swk);
        float4* d1 = reinterpret_cast<float4*>(swv);
        for (int i = tid; i < 1024; i += TPB) { d0[i] = s0[i]; d1[i] = s1[i]; }
        if (tid < 64) { sbk[tid] = bk[tid]; sbv[tid] = bv[tid]; }
    }
    __syncthreads();

    const int pm    = tid & 63;        // (p*8 + m) this thread reduces
    const int p8    = pm & 56;         // p*8
    const int slice = tid >> 6;        // 0/1 : pixel half

    for (int tile = blockIdx.x; tile < NTILES; tile += gridDim.x) {
        const int b = tile / TPB_PER_BATCH;
        const int n = (tile % TPB_PER_BATCH) * TILE + tid;
        const float* xb = low + (b * Cc) * Np + n;

        // load this pixel's 64 input channels, packed into 32 f32x2
        u64 x2[32];
#pragma unroll
        for (int c = 0; c < 32; c++) {
            float a  = xb[(2 * c)     * Np];
            float bb = xb[(2 * c + 1) * Np];
            x2[c] = pk2(a, bb);
        }

        __syncthreads();  // previous tile's stage-B readers are done

        // stage A: k,v convolutions -> staged into sK/sV (transposed layout)
#pragma unroll 2
        for (int oc = 0; oc < 64; oc++) {
            float kraw = dot64(x2, swk + oc * 64) + sbk[oc];
            sK[oc * PITCH + tid] = softplus(kraw);
            float vraw = dot64(x2, swv + oc * 64) + sbv[oc];
            sV[oc * PITCH + tid] = vraw;
        }
        __syncthreads();

        // stage B: this thread owns (p,m, pixel-half): accumulate over 64 pixels
        float acc[8] = {0, 0, 0, 0, 0, 0, 0, 0};
        float ks = 0.0f;
        const float* kr = sK + pm * PITCH + slice * 64;
        const float* vr = sV + p8 * PITCH + slice * 64;
#pragma unroll 8
        for (int i = 0; i < 64; i++) {
            float kvl = kr[i];
            ks += kvl;
#pragma unroll
            for (int c = 0; c < 8; c++) acc[c] += kvl * vr[c * PITCH + i];
        }
        float* ga = g_attn + (b * 64 + pm) * 8;
#pragma unroll
        for (int c = 0; c < 8; c++) atomicAdd(ga + c, acc[c]);
        atomicAdd(g_ksum + b * 64 + pm, ks);
    }
}

// ---------------------------------------------------------------------------
// Pass 2: q convs + attention apply + output conv. Static smem (~35 KB).
__global__ __launch_bounds__(TPB)
void pass2_out(const float* __restrict__ high, const float* __restrict__ low,
               const float* __restrict__ wqh, const float* __restrict__ bqh,
               const float* __restrict__ wql, const float* __restrict__ bql,
               const float* __restrict__ wo,  const float* __restrict__ bo,
               float* __restrict__ out) {
    __shared__ float swh[2048];
    __shared__ float swl[2048];
    __shared__ float swo[4096];
    __shared__ float sbh[32], sbl[32], sbo[64];
    __shared__ float sA[512];
    __shared__ float sks[64];

    const int tid = threadIdx.x;

    {
        const float4* s0 = reinterpret_cast<const float4*>(wqh);
        const float4* s1 = reinterpret_cast<const float4*>(wql);
        const float4* s2 = reinterpret_cast<const float4*>(wo);
        float4* d0 = reinterpret_cast<float4*>(swh);
        float4* d1 = reinterpret_cast<float4*>(swl);
        float4* d2 = reinterpret_cast<float4*>(swo);
        for (int i = tid; i < 512; i += TPB) { d0[i] = s0[i]; d1[i] = s1[i]; }
        for (int i = tid; i < 1024; i += TPB) d2[i] = s2[i];
        if (tid < 32) { sbh[tid] = bqh[tid]; sbl[tid] = bql[tid]; }
        if (tid < 64) { sbo[tid] = bo[tid]; }
    }

    for (int tile = blockIdx.x; tile < NTILES; tile += gridDim.x) {
        const int b = tile / TPB_PER_BATCH;
        const int n = (tile % TPB_PER_BATCH) * TILE + tid;

        __syncthreads();  // protect sA/sks against previous iteration readers
        if (tid < 64) sks[tid] = g_ksum[b * 64 + tid] + EPSV;
        for (int i = tid; i < 512; i += TPB) sA[i] = g_attn[b * 512 + i];
        __syncthreads();

        // ---- q = softplus([wqh@high ; wql@low]) ----
        float q[64];
        {
            const float* xb = high + (b * Cc) * Np + n;
            u64 x2[32];
#pragma unroll
            for (int c = 0; c < 32; c++)
                x2[c] = pk2(xb[(2 * c) * Np], xb[(2 * c + 1) * Np]);
#pragma unroll
            for (int o = 0; o < 32; o++)
                q[o] = softplus(dot64(x2, swh + o * 64) + sbh[o]);

            xb = low + (b * Cc) * Np + n;
#pragma unroll
            for (int c = 0; c < 32; c++)
                x2[c] = pk2(xb[(2 * c) * Np], xb[(2 * c + 1) * Np]);
#pragma unroll
            for (int o = 0; o < 32; o++)
                q[32 + o] = softplus(dot64(x2, swl + o * 64) + sbl[o]);
        }

        // ---- per-head: norm and t = norm * (q @ attn) ----
        float t[64];
#pragma unroll
        for (int p = 0; p < 8; p++) {
            float nm = 0.0f;
#pragma unroll
            for (int m = 0; m < 8; m++) nm += q[p * 8 + m] * sks[p * 8 + m];
            float inv = 1.0f / nm;
#pragma unroll
            for (int c = 0; c < 8; c++) {
                float a = 0.0f;
#pragma unroll
                for (int m = 0; m < 8; m++)
                    a += q[p * 8 + m] * sA[(p * 8 + m) * 8 + c];
                t[p * 8 + c] = a * inv;
            }
        }

        // ---- y = wo @ t + bo ----
        u64 t2[32];
#pragma unroll
        for (int i = 0; i < 32; i++) t2[i] = pk2(t[2 * i], t[2 * i + 1]);

        float* ob = out + (b * Cc) * Np + n;
#pragma unroll 2
        for (int o = 0; o < 64; o++) {
            ob[o * Np] = dot64(t2, swo + o * 64) + sbo[o];
        }
    }
}

constexpr int P1_SMEM_BYTES = (8320 + 2 * 64 * PITCH) * 4;  // ~97 KB

}  // namespace mca

// ---------------------------------------------------------------------------
extern "C" void kernel_launch(void* const* d_in, const int* in_sizes, int n_in,
                              void* d_out, int out_size) {
    using namespace mca;
    (void)in_sizes; (void)n_in; (void)out_size;

    const float* high = (const float*)d_in[0];
    const float* low  = (const float*)d_in[1];
    const float* wqh  = (const float*)d_in[2];
    const float* bqh  = (const float*)d_in[3];
    const float* wql  = (const float*)d_in[4];
    const float* bql  = (const float*)d_in[5];
    const float* wk   = (const float*)d_in[6];
    const float* bk   = (const float*)d_in[7];
    const float* wv   = (const float*)d_in[8];
    const float* bv   = (const float*)d_in[9];
    const float* wo   = (const float*)d_in[10];
    const float* bo   = (const float*)d_in[11];
    float* out = (float*)d_out;

    // idempotent, host-side (not a stream op) -> capture-safe
    cudaFuncSetAttribute(pass1_kv, cudaFuncAttributeMaxDynamicSharedMemorySize,
                         P1_SMEM_BYTES);

    zero_scratch<<<1, 512>>>();
    pass1_kv<<<296, TPB, P1_SMEM_BYTES>>>(low, wk, bk, wv, bv);
    pass2_out<<<592, TPB>>>(high, low, wqh, bqh, wql, bql, wo, bo, out);
}